// round 14
// baseline (speedup 1.0000x reference)
#include <cuda_runtime.h>
#include <stdint.h>
#include <math.h>

#define T_LEN 8192
#define B_CNT 16
#define NSTEP 8189            // T-3 markov samples
#define SEG_N 128
#define SEG_L 64              // SEG_N*SEG_L = 8192 (pad last 3 steps)
#define SMP_STRIDE 8208       // 16-byte lead pad + 8192
#define NB 512                // k12 blocks (all resident: 512 < 148*8)

// ---------------- device scratch (no allocations allowed) ----------------
__device__ uint8_t g_snsp[B_CNT * T_LEN];        // per (b,t): sn | sp<<2
__device__ uint8_t g_smp[B_CNT * SMP_STRIDE];    // [16B pad][8192 samples] per b
__device__ unsigned long long g_barctr = 0ull;   // monotonic grid barrier counter

// ---------------- grid-wide barrier (all NB blocks resident) ----------------
__device__ __forceinline__ void gbar() {
    __threadfence();                  // release my writes
    __syncthreads();
    if (threadIdx.x == 0) {
        unsigned long long old = atomicAdd(&g_barctr, 1ull);
        unsigned long long target = (old / NB + 1ull) * NB;
        while (*(volatile unsigned long long*)&g_barctr < target) __nanosleep(32);
    }
    __syncthreads();
}

// ---------------- threefry-2x32 (20 rounds), matches JAX exactly ----------------
__device__ __forceinline__ void tf2x32(uint32_t k0, uint32_t k1,
                                       uint32_t x0, uint32_t x1,
                                       uint32_t& o0, uint32_t& o1) {
    uint32_t ks2 = k0 ^ k1 ^ 0x1BD11BDAu;
    x0 += k0; x1 += k1;
#define RND(r) { x0 += x1; x1 = __funnelshift_l(x1, x1, (r)); x1 ^= x0; }
    RND(13) RND(15) RND(26) RND(6)
    x0 += k1; x1 += ks2 + 1u;
    RND(17) RND(29) RND(16) RND(24)
    x0 += ks2; x1 += k0 + 2u;
    RND(13) RND(15) RND(26) RND(6)
    x0 += k0; x1 += k1 + 3u;
    RND(17) RND(29) RND(16) RND(24)
    x0 += k1; x1 += ks2 + 4u;
    RND(13) RND(15) RND(26) RND(6)
    x0 += ks2; x1 += k0 + 5u;
#undef RND
    o0 = x0; o1 = x1;
}

// JAX uniform(minval=tiny, maxval=1) from raw bits
__device__ __forceinline__ float u_from_bits(uint32_t bits) {
    const float tiny = 1.1754943508222875e-38f;  // FLT_MIN
    float f = __uint_as_float((bits >> 9) | 0x3f800000u) - 1.0f;
    return fmaxf(tiny, f + tiny);
}

// accurate FP32 log (~1-2 ulp), fast-math-proof: atanh kernel + Cody-Waite ln2
__device__ __forceinline__ float alog(float x) {
    int ix = __float_as_int(x);
    int e = ((ix >> 23) & 255) - 127;
    float m = __int_as_float((ix & 0x007FFFFF) | 0x3F800000);  // [1,2)
    if (m > 1.33333337f) { m = m * 0.5f; e += 1; }             // m in [2/3, 4/3]
    float s = (m - 1.0f) / (m + 1.0f);                          // |s| <= 0.2
    float s2 = s * s;
    float P = fmaf(s2, 0.11111111f, 0.14285715f);
    P = fmaf(s2, P, 0.19999999f);
    P = fmaf(s2, P, 0.33333334f);
    float logm = fmaf(2.0f * s * s2, P, 2.0f * s);
    float fe = (float)e;
    float r = fmaf(fe, 1.42860677e-6f, logm);        // + e*ln2_lo
    return fmaf(fe, 0.693145751953125f, r);          // + e*ln2_hi
}

__device__ __forceinline__ float gum_acc(uint32_t bits) {
    float u = u_from_bits(bits);
    return -alog(-alog(u));
}

// correctly-rounded f32 gumbel via double logs (only when argmax margin is tight)
__device__ __noinline__ float gum_precise(uint32_t bits) {
    float u = u_from_bits(bits);
    float inner = (float)log((double)u);
    return -(float)log((double)(-inner));
}

// ---------------- K12: samples + chain in ONE kernel (grid barrier between) -------
__global__ void __launch_bounds__(256) k12_gen_chain(const int* __restrict__ seed_ptr) {
    __shared__ uint32_t sk0[16], sk1[16];
    __shared__ float slog[4];
    int tid = threadIdx.x;

    // ======== phase 1: per-(t,b) candidate samples (round-4/13 form) ========
    {
        int tloc = tid & 15;
        int b = tid >> 4;
        int t = blockIdx.x * 16 + tloc;

        if (tid < 16) {       // keys[t] = tf(key, 0, t)  (partitionable split)
            uint32_t a0, a1;
            tf2x32(0u, (uint32_t)(*seed_ptr), 0u, (uint32_t)(blockIdx.x * 16 + tid), a0, a1);
            sk0[tid] = a0; sk1[tid] = a1;
        } else if (tid >= 32 && tid < 36) {   // logits, built like the numpy reference
            double p = 0.1, s = 1.0 - 2.0 * 0.1;
            int k = tid - 32;
            double v = (k == 0) ? (double)(float)p
                     : (k == 1) ? (double)(float)s
                     : (k == 2) ? (double)(float)(s / (p + s))
                                : (double)(float)(p / (p + s));
            slog[k] = (float)log(v);
        }
        __syncthreads();

        if (t >= NSTEP) {     // pad steps 8189..8191 (never affect the output)
            g_snsp[b * T_LEN + t] = (uint8_t)(1u | (1u << 2));
        } else {
            uint32_t kt0 = sk0[tloc], kt1 = sk1[tloc];
            uint32_t bt[3];
#pragma unroll
            for (int k = 0; k < 3; k++) {   // bits[(16,3)][3b+k] = o0^o1 of tf(key_t,0,j)
                uint32_t o0, o1;
                tf2x32(kt0, kt1, 0u, (uint32_t)(3 * b + k), o0, o1);
                bt[k] = o0 ^ o1;
            }
            float lp = slog[0], ls = slog[1], l21 = slog[2], l22 = slog[3];

            float g0 = gum_acc(bt[0]), g1 = gum_acc(bt[1]), g2 = gum_acc(bt[2]);
            float v0 = lp + g0, v1 = ls + g1, v2 = lp + g2;
            float w1 = l21 + g1, w2 = l22 + g2;

            float mmin = fminf(fminf(fabsf(v0 - v1), fabsf(v0 - v2)),
                               fminf(fabsf(v1 - v2), fabsf(w1 - w2)));
            if (mmin < 3e-5f) {   // tight argmax margin: redo exactly (DP logs, ~never)
                g0 = gum_precise(bt[0]); g1 = gum_precise(bt[1]); g2 = gum_precise(bt[2]);
                v0 = lp + g0; v1 = ls + g1; v2 = lp + g2;
                w1 = l21 + g1; w2 = l22 + g2;
            }
            int sn = 0; float best = v0;              // jnp.argmax first-max semantics
            if (v1 > best) { best = v1; sn = 1; }
            if (v2 > best) { sn = 2; }
            int sp = (w1 >= w2) ? 1 : 2;              // special row [-inf, w1, w2]
            g_snsp[b * T_LEN + t] = (uint8_t)(sn | (sp << 2));
        }
    }
    gbar();

    // ======== phase 2: chain resolve (blocks 0..15 only; one block per batch) ======
    if (blockIdx.x < B_CNT) {
        __shared__ uint8_t s_end[SEG_N][9];
        __shared__ unsigned long long s_map[SEG_N];
        int b = blockIdx.x;

        // spec: 1152 (seg, s0) items over 256 threads; 64-step segments
#pragma unroll
        for (int base = 0; base < 1152; base += 256) {
            int item = base + tid;
            if (item < 1152) {
                int seg = item / 9, s0 = item % 9;
                const uint4* src = (const uint4*)(g_snsp + b * T_LEN + seg * SEG_L);
                uint4 w[4];
#pragma unroll
                for (int q = 0; q < 4; q++) w[q] = __ldg(&src[q]);
                uint32_t cc = (((uint32_t)(s0 / 3)) << 2) | (uint32_t)(s0 % 3);
#pragma unroll
                for (int q = 0; q < 4; q++) {
                    uint32_t ws[4] = {w[q].x, w[q].y, w[q].z, w[q].w};
#pragma unroll
                    for (int wi = 0; wi < 4; wi++) {
                        uint32_t word = ws[wi];
#pragma unroll
                        for (int bi = 0; bi < 4; bi++) {
                            uint32_t byte = word >> (8 * bi);
                            uint32_t s = (cc == 9u) ? ((byte >> 2) & 3u) : (byte & 3u);
                            cc = (s << 2) | (cc >> 2);
                        }
                    }
                }
                s_end[seg][s0] = (uint8_t)((cc >> 2) * 3u + (cc & 3u));
            }
        }
        __syncthreads();

        if (tid < SEG_N) {        // pack nibble maps
            unsigned long long m = 0ull;
#pragma unroll
            for (int i = 0; i < 9; i++)
                m |= (unsigned long long)s_end[tid][i] << (4 * i);
            s_map[tid] = m;
        }
        __syncthreads();

        // Kogge-Stone inclusive prefix: s_map[i] = m_i ∘ ... ∘ m_0
#pragma unroll
        for (int d = 1; d < SEG_N; d <<= 1) {
            unsigned long long v = 0ull;
            if (tid < SEG_N) {
                v = s_map[tid];
                if (tid >= d) {
                    unsigned long long g = s_map[tid - d], f = v, r = 0ull;
#pragma unroll
                    for (int i = 0; i < 9; i++) {
                        uint32_t gi = (uint32_t)(g >> (4 * i)) & 15u;
                        uint32_t fi = (uint32_t)(f >> (4 * gi)) & 15u;
                        r |= (unsigned long long)fi << (4 * i);
                    }
                    v = r;
                }
            }
            __syncthreads();
            if (tid < SEG_N) s_map[tid] = v;
            __syncthreads();
        }

        if (tid == 0) g_smp[b * SMP_STRIDE + 15] = 1;   // pad byte: m(to=0) = 1

        if (tid < SEG_N) {        // replay with true start
            int seg = tid;
            int i0 = (seg == 0) ? 4 : (int)((s_map[seg - 1] >> 16) & 15ull);
            const uint4* src = (const uint4*)(g_snsp + b * T_LEN + seg * SEG_L);
            uint4 w[4];
#pragma unroll
            for (int q = 0; q < 4; q++) w[q] = __ldg(&src[q]);
            uint32_t cc = (((uint32_t)(i0 / 3)) << 2) | (uint32_t)(i0 % 3);
            uint4* dst = (uint4*)(g_smp + b * SMP_STRIDE + 16 + seg * SEG_L);
#pragma unroll
            for (int q = 0; q < 4; q++) {
                uint32_t in[4] = {w[q].x, w[q].y, w[q].z, w[q].w};
                uint32_t o[4];
#pragma unroll
                for (int wi = 0; wi < 4; wi++) {
                    uint32_t word = in[wi], ow = 0u;
#pragma unroll
                    for (int bi = 0; bi < 4; bi++) {
                        uint32_t s = (cc == 9u) ? ((word >> (8 * bi + 2)) & 3u)
                                                : ((word >> (8 * bi)) & 3u);
                        cc = (s << 2) | (cc >> 2);
                        ow |= s << (8 * bi);
                    }
                    o[wi] = ow;
                }
                dst[q] = make_uint4(o[0], o[1], o[2], o[3]);
            }
        }
    }
}

// ---------------- K4: vectorized gather (4 outputs / thread; round-3 form) --------
// out[bi, to] = x[bi, to + m(b,to)];  m bytes live at g_smp[b*STRIDE + 15 + to]
__global__ void k4_gather(const float* __restrict__ x, float* __restrict__ out) {
    int t = blockIdx.x * blockDim.x + threadIdx.x;   // quad index: outputs 4t..4t+3
    int bi = blockIdx.y;                             // b*256 + i
    int b = bi >> 8;

    // m bytes for j=0..3 are at byte positions 4t+15 .. 4t+18 -> words t+3, t+4
    const uint32_t* mw = (const uint32_t*)(g_smp + b * SMP_STRIDE);
    uint32_t w0 = __ldg(&mw[t + 3]);
    uint32_t w1 = __ldg(&mw[t + 4]);
    uint32_t mword = __funnelshift_r(w0, w1, 24);    // byte j = m for output 4t+j

    const float* xr = x + (size_t)bi * 8192 + 4 * t;
    float4 v = *(const float4*)xr;                   // 16B aligned
    float v4 = 0.f, v5 = 0.f;
    bool full = (t < 2047);
    if (full) { float2 ex = *(const float2*)(xr + 4); v4 = ex.x; v5 = ex.y; }

    uint32_t m0 = mword & 3u, m1 = (mword >> 8) & 3u,
             m2 = (mword >> 16) & 3u, m3 = (mword >> 24) & 3u;
    float o0 = (m0 == 0u) ? v.x : ((m0 == 1u) ? v.y : v.z);
    float o1 = (m1 == 0u) ? v.y : ((m1 == 1u) ? v.z : v.w);
    float o2 = (m2 == 0u) ? v.z : ((m2 == 1u) ? v.w : v4);
    float o3 = (m3 == 0u) ? v.w : ((m3 == 1u) ? v4 : v5);

    float2* orow = (float2*)(out + (size_t)bi * 8190 + 4 * t);  // 8B aligned
    __stcs(&orow[0], make_float2(o0, o1));
    if (full) __stcs(&orow[1], make_float2(o2, o3));
}

extern "C" void kernel_launch(void* const* d_in, const int* in_sizes, int n_in,
                              void* d_out, int out_size) {
    const float* x = (const float*)d_in[0];
    const int* seed = (const int*)d_in[1];
    float* out = (float*)d_out;

    k12_gen_chain<<<NB, 256>>>(seed);     // samples + grid barrier + chain resolve
    dim3 grid(8, 4096);                   // 8*256 = 2048 quads per row
    k4_gather<<<grid, 256>>>(x, out);
}

// round 15
// speedup vs baseline: 1.0350x; 1.0350x over previous
#include <cuda_runtime.h>
#include <stdint.h>
#include <math.h>

#define T_LEN 8192
#define B_CNT 16
#define NSTEP 8189            // T-3 markov samples
#define SEG_N 64
#define SEG_L 128             // SEG_N*SEG_L = 8192 (pad last 3 steps)
#define SMP_STRIDE 8208       // 16-byte lead pad + 8192

// ---------------- device scratch (no allocations allowed) ----------------
__device__ uint8_t g_snsp[B_CNT * T_LEN];        // per (b,t): sn | sp<<2
__device__ uint8_t g_smp[B_CNT * SMP_STRIDE];    // [16B pad][8192 samples] per b

// ---------------- threefry-2x32 (20 rounds), matches JAX exactly ----------------
__device__ __forceinline__ void tf2x32(uint32_t k0, uint32_t k1,
                                       uint32_t x0, uint32_t x1,
                                       uint32_t& o0, uint32_t& o1) {
    uint32_t ks2 = k0 ^ k1 ^ 0x1BD11BDAu;
    x0 += k0; x1 += k1;
#define RND(r) { x0 += x1; x1 = __funnelshift_l(x1, x1, (r)); x1 ^= x0; }
    RND(13) RND(15) RND(26) RND(6)
    x0 += k1; x1 += ks2 + 1u;
    RND(17) RND(29) RND(16) RND(24)
    x0 += ks2; x1 += k0 + 2u;
    RND(13) RND(15) RND(26) RND(6)
    x0 += k0; x1 += k1 + 3u;
    RND(17) RND(29) RND(16) RND(24)
    x0 += k1; x1 += ks2 + 4u;
    RND(13) RND(15) RND(26) RND(6)
    x0 += ks2; x1 += k0 + 5u;
#undef RND
    o0 = x0; o1 = x1;
}

// JAX uniform(minval=tiny, maxval=1) from raw bits
__device__ __forceinline__ float u_from_bits(uint32_t bits) {
    const float tiny = 1.1754943508222875e-38f;  // FLT_MIN
    float f = __uint_as_float((bits >> 9) | 0x3f800000u) - 1.0f;
    return fmaxf(tiny, f + tiny);
}

// accurate FP32 log (~1-2 ulp), fast-math-proof: atanh kernel + Cody-Waite ln2
__device__ __forceinline__ float alog(float x) {
    int ix = __float_as_int(x);
    int e = ((ix >> 23) & 255) - 127;
    float m = __int_as_float((ix & 0x007FFFFF) | 0x3F800000);  // [1,2)
    if (m > 1.33333337f) { m = m * 0.5f; e += 1; }             // m in [2/3, 4/3]
    float s = (m - 1.0f) / (m + 1.0f);                          // |s| <= 0.2
    float s2 = s * s;
    float P = fmaf(s2, 0.11111111f, 0.14285715f);
    P = fmaf(s2, P, 0.19999999f);
    P = fmaf(s2, P, 0.33333334f);
    float logm = fmaf(2.0f * s * s2, P, 2.0f * s);
    float fe = (float)e;
    float r = fmaf(fe, 1.42860677e-6f, logm);        // + e*ln2_lo
    return fmaf(fe, 0.693145751953125f, r);          // + e*ln2_hi
}

__device__ __forceinline__ float gum_acc(uint32_t bits) {
    float u = u_from_bits(bits);
    return -alog(-alog(u));
}

// correctly-rounded f32 gumbel via double logs (only when argmax margin is tight)
__device__ __noinline__ float gum_precise(uint32_t bits) {
    float u = u_from_bits(bits);
    float inner = (float)log((double)u);
    return -(float)log((double)(-inner));
}

// ---------------- K1: per-(t,b) candidate samples sn / sp (round-4 form) ----------
// block = 16 t-values x 16 batches; keys[t] + the 4 logit constants in smem.
__global__ void __launch_bounds__(256) k1_gen(const int* __restrict__ seed_ptr) {
    __shared__ uint32_t sk0[16], sk1[16];
    __shared__ float slog[4];
    int tid = threadIdx.x;
    int tloc = tid & 15;
    int b = tid >> 4;
    int t = blockIdx.x * 16 + tloc;

    if (tid < 16) {       // keys[t] = tf(key, 0, t)  (partitionable split)
        uint32_t a0, a1;
        tf2x32(0u, (uint32_t)(*seed_ptr), 0u, (uint32_t)(blockIdx.x * 16 + tid), a0, a1);
        sk0[tid] = a0; sk1[tid] = a1;
    } else if (tid >= 32 && tid < 36) {   // logits, built like the numpy reference
        double p = 0.1, s = 1.0 - 2.0 * 0.1;
        int k = tid - 32;
        double v = (k == 0) ? (double)(float)p
                 : (k == 1) ? (double)(float)s
                 : (k == 2) ? (double)(float)(s / (p + s))
                            : (double)(float)(p / (p + s));
        slog[k] = (float)log(v);
    }
    __syncthreads();

    if (t >= NSTEP) {     // pad steps 8189..8191 (never affect the output)
        g_snsp[b * T_LEN + t] = (uint8_t)(1u | (1u << 2));
        return;
    }
    uint32_t kt0 = sk0[tloc], kt1 = sk1[tloc];

    uint32_t bt[3];
#pragma unroll
    for (int k = 0; k < 3; k++) {   // bits[(16,3)][3b+k] = o0^o1 of tf(key_t, 0, j)
        uint32_t o0, o1;
        tf2x32(kt0, kt1, 0u, (uint32_t)(3 * b + k), o0, o1);
        bt[k] = o0 ^ o1;
    }

    float lp = slog[0], ls = slog[1], l21 = slog[2], l22 = slog[3];

    float g0 = gum_acc(bt[0]), g1 = gum_acc(bt[1]), g2 = gum_acc(bt[2]);
    float v0 = lp + g0, v1 = ls + g1, v2 = lp + g2;
    float w1 = l21 + g1, w2 = l22 + g2;

    float mmin = fminf(fminf(fabsf(v0 - v1), fabsf(v0 - v2)),
                       fminf(fabsf(v1 - v2), fabsf(w1 - w2)));
    if (mmin < 3e-5f) {   // tight argmax margin: redo exactly (DP logs, ~never)
        g0 = gum_precise(bt[0]); g1 = gum_precise(bt[1]); g2 = gum_precise(bt[2]);
        v0 = lp + g0; v1 = ls + g1; v2 = lp + g2;
        w1 = l21 + g1; w2 = l22 + g2;
    }

    int sn = 0; float best = v0;              // jnp.argmax first-max semantics
    if (v1 > best) { best = v1; sn = 1; }
    if (v2 > best) { sn = 2; }
    int sp = (w1 >= w2) ? 1 : 2;              // special row [-inf, w1, w2]

    g_snsp[b * T_LEN + t] = (uint8_t)(sn | (sp << 2));
}

// compose two 9-state maps packed as nibbles: (f ∘ g)(i) = f[g[i]]
__device__ __forceinline__ unsigned long long map_comp(unsigned long long f,
                                                       unsigned long long g) {
    unsigned long long r = 0ull;
#pragma unroll
    for (int i = 0; i < 9; i++) {
        uint32_t gi = (uint32_t)(g >> (4 * i)) & 15u;
        uint32_t fi = (uint32_t)(f >> (4 * gi)) & 15u;
        r |= (unsigned long long)fi << (4 * i);
    }
    return r;
}

// ---------------- K2: fused speculative chain (one block per batch) ----------------
__global__ void __launch_bounds__(576) k2_chain() {
    __shared__ uint8_t s_end[SEG_N][9];
    __shared__ unsigned long long s_map[SEG_N];
    int b = blockIdx.x;
    int tid = threadIdx.x;

    {   // ---- phase A: 64 segs x 9 speculative start states ----
        int seg = tid / 9, s0 = tid % 9;
        const uint4* src = (const uint4*)(g_snsp + b * T_LEN + seg * SEG_L);
        uint4 w[8];
#pragma unroll
        for (int q = 0; q < 8; q++) w[q] = __ldg(&src[q]);   // MLP=8 up front
        uint32_t cc = (((uint32_t)(s0 / 3)) << 2) | (uint32_t)(s0 % 3);
#pragma unroll
        for (int q = 0; q < 8; q++) {
            uint32_t ws[4] = {w[q].x, w[q].y, w[q].z, w[q].w};
#pragma unroll
            for (int wi = 0; wi < 4; wi++) {
                uint32_t word = ws[wi];
#pragma unroll
                for (int bi = 0; bi < 4; bi++) {
                    uint32_t byte = word >> (8 * bi);
                    uint32_t s = (cc == 9u) ? ((byte >> 2) & 3u) : (byte & 3u);
                    cc = (s << 2) | (cc >> 2);
                }
            }
        }
        s_end[seg][s0] = (uint8_t)((cc >> 2) * 3u + (cc & 3u));
    }
    __syncthreads();

    if (tid < SEG_N) {    // pack 9 end states into one nibble map
        unsigned long long m = 0ull;
#pragma unroll
        for (int i = 0; i < 9; i++)
            m |= (unsigned long long)s_end[tid][i] << (4 * i);
        s_map[tid] = m;
    }
    __syncthreads();

    // ---- phase B: Kogge-Stone inclusive prefix s_map[i] = m_i ∘ ... ∘ m_0 ----
#pragma unroll
    for (int d = 1; d < SEG_N; d <<= 1) {
        unsigned long long v;
        if (tid < SEG_N) {
            v = s_map[tid];
            if (tid >= d) v = map_comp(v, s_map[tid - d]);
        }
        __syncthreads();
        if (tid < SEG_N) s_map[tid] = v;
        __syncthreads();
    }

    if (tid == 0) g_smp[b * SMP_STRIDE + 15] = 1;   // pad byte: m(to=0) = 1

    if (tid < SEG_N) {    // ---- phase C: replay with true start ----
        int seg = tid;
        int i0 = (seg == 0) ? 4 : (int)((s_map[seg - 1] >> 16) & 15ull);
        const uint4* src = (const uint4*)(g_snsp + b * T_LEN + seg * SEG_L);
        uint4 w[8];
#pragma unroll
        for (int q = 0; q < 8; q++) w[q] = __ldg(&src[q]);
        uint32_t cc = (((uint32_t)(i0 / 3)) << 2) | (uint32_t)(i0 % 3);
        uint4* dst = (uint4*)(g_smp + b * SMP_STRIDE + 16 + seg * SEG_L);
#pragma unroll
        for (int q = 0; q < 8; q++) {
            uint32_t in[4] = {w[q].x, w[q].y, w[q].z, w[q].w};
            uint32_t out[4];
#pragma unroll
            for (int wi = 0; wi < 4; wi++) {
                uint32_t word = in[wi], ow = 0u;
#pragma unroll
                for (int bi = 0; bi < 4; bi++) {
                    uint32_t s = (cc == 9u) ? ((word >> (8 * bi + 2)) & 3u)
                                            : ((word >> (8 * bi)) & 3u);
                    cc = (s << 2) | (cc >> 2);
                    ow |= s << (8 * bi);
                }
                out[wi] = ow;
            }
            dst[q] = make_uint4(out[0], out[1], out[2], out[3]);
        }
    }
}

// ---------------- K4: vectorized gather (4 outputs / thread) ----------------------
// out[bi, to] = x[bi, to + m(b,to)];  m bytes live at g_smp[b*STRIDE + 15 + to]
// Even bi rows: output quad is 16B-aligned -> single STG.128.
__global__ void k4_gather(const float* __restrict__ x, float* __restrict__ out) {
    int t = blockIdx.x * blockDim.x + threadIdx.x;   // quad index: outputs 4t..4t+3
    int bi = blockIdx.y;                             // b*256 + i
    int b = bi >> 8;

    // m bytes for j=0..3 are at byte positions 4t+15 .. 4t+18 -> words t+3, t+4
    const uint32_t* mw = (const uint32_t*)(g_smp + b * SMP_STRIDE);
    uint32_t w0 = __ldg(&mw[t + 3]);
    uint32_t w1 = __ldg(&mw[t + 4]);
    uint32_t mword = __funnelshift_r(w0, w1, 24);    // byte j = m for output 4t+j

    const float* xr = x + (size_t)bi * 8192 + 4 * t;
    float4 v = *(const float4*)xr;                   // 16B aligned
    float v4 = 0.f, v5 = 0.f;
    bool full = (t < 2047);
    if (full) { float2 ex = *(const float2*)(xr + 4); v4 = ex.x; v5 = ex.y; }

    uint32_t m0 = mword & 3u, m1 = (mword >> 8) & 3u,
             m2 = (mword >> 16) & 3u, m3 = (mword >> 24) & 3u;
    float o0 = (m0 == 0u) ? v.x : ((m0 == 1u) ? v.y : v.z);
    float o1 = (m1 == 0u) ? v.y : ((m1 == 1u) ? v.z : v.w);
    float o2 = (m2 == 0u) ? v.z : ((m2 == 1u) ? v.w : v4);
    float o3 = (m3 == 0u) ? v.w : ((m3 == 1u) ? v4 : v5);

    float* orow = out + (size_t)bi * 8190 + 4 * t;
    bool al16 = ((bi & 1) == 0);                     // even rows: 16B-aligned
    if (full & al16) {
        __stcs((float4*)orow, make_float4(o0, o1, o2, o3));
    } else {
        __stcs((float2*)orow, make_float2(o0, o1));
        if (full) __stcs((float2*)(orow + 2), make_float2(o2, o3));
    }
}

extern "C" void kernel_launch(void* const* d_in, const int* in_sizes, int n_in,
                              void* d_out, int out_size) {
    const float* x = (const float*)d_in[0];
    const int* seed = (const int*)d_in[1];
    float* out = (float*)d_out;

    k1_gen<<<512, 256>>>(seed);           // 512 blocks of (16 t x 16 b), logits fused
    k2_chain<<<16, 576>>>();              // one block per batch: spec + prefix + replay
    dim3 grid(8, 4096);                   // 8*256 = 2048 quads per row
    k4_gather<<<grid, 256>>>(x, out);
}

// round 16
// speedup vs baseline: 1.0725x; 1.0363x over previous
#include <cuda_runtime.h>
#include <stdint.h>
#include <math.h>

#define T_LEN 8192
#define B_CNT 16
#define NSTEP 8189            // T-3 markov samples
#define SEG_N 64
#define SEG_L 128             // SEG_N*SEG_L = 8192 (pad last 3 steps)
#define SMP_STRIDE 8208       // 16-byte lead pad + 8192

// ---------------- device scratch (no allocations allowed) ----------------
__device__ uint8_t g_snsp[B_CNT * T_LEN];        // per (b,t): sn | sp<<2
__device__ uint8_t g_smp[B_CNT * SMP_STRIDE];    // [16B pad][8192 samples] per b

// ---------------- threefry-2x32 (20 rounds), matches JAX exactly ----------------
__device__ __forceinline__ void tf2x32(uint32_t k0, uint32_t k1,
                                       uint32_t x0, uint32_t x1,
                                       uint32_t& o0, uint32_t& o1) {
    uint32_t ks2 = k0 ^ k1 ^ 0x1BD11BDAu;
    x0 += k0; x1 += k1;
#define RND(r) { x0 += x1; x1 = __funnelshift_l(x1, x1, (r)); x1 ^= x0; }
    RND(13) RND(15) RND(26) RND(6)
    x0 += k1; x1 += ks2 + 1u;
    RND(17) RND(29) RND(16) RND(24)
    x0 += ks2; x1 += k0 + 2u;
    RND(13) RND(15) RND(26) RND(6)
    x0 += k0; x1 += k1 + 3u;
    RND(17) RND(29) RND(16) RND(24)
    x0 += k1; x1 += ks2 + 4u;
    RND(13) RND(15) RND(26) RND(6)
    x0 += ks2; x1 += k0 + 5u;
#undef RND
    o0 = x0; o1 = x1;
}

// JAX uniform(minval=tiny, maxval=1) from raw bits
__device__ __forceinline__ float u_from_bits(uint32_t bits) {
    const float tiny = 1.1754943508222875e-38f;  // FLT_MIN
    float f = __uint_as_float((bits >> 9) | 0x3f800000u) - 1.0f;
    return fmaxf(tiny, f + tiny);
}

// accurate FP32 log (~1-2 ulp), fast-math-proof: atanh kernel + Cody-Waite ln2
__device__ __forceinline__ float alog(float x) {
    int ix = __float_as_int(x);
    int e = ((ix >> 23) & 255) - 127;
    float m = __int_as_float((ix & 0x007FFFFF) | 0x3F800000);  // [1,2)
    if (m > 1.33333337f) { m = m * 0.5f; e += 1; }             // m in [2/3, 4/3]
    float s = (m - 1.0f) / (m + 1.0f);                          // |s| <= 0.2
    float s2 = s * s;
    float P = fmaf(s2, 0.11111111f, 0.14285715f);
    P = fmaf(s2, P, 0.19999999f);
    P = fmaf(s2, P, 0.33333334f);
    float logm = fmaf(2.0f * s * s2, P, 2.0f * s);
    float fe = (float)e;
    float r = fmaf(fe, 1.42860677e-6f, logm);        // + e*ln2_lo
    return fmaf(fe, 0.693145751953125f, r);          // + e*ln2_hi
}

__device__ __forceinline__ float gum_acc(uint32_t bits) {
    float u = u_from_bits(bits);
    return -alog(-alog(u));
}

// correctly-rounded f32 gumbel via double logs (only when argmax margin is tight)
__device__ __noinline__ float gum_precise(uint32_t bits) {
    float u = u_from_bits(bits);
    float inner = (float)log((double)u);
    return -(float)log((double)(-inner));
}

// ---------------- K1: per-(t,b) candidate samples sn / sp (round-4 form) ----------
// block = 16 t-values x 16 batches; keys[t] + the 4 logit constants in smem.
__global__ void __launch_bounds__(256) k1_gen(const int* __restrict__ seed_ptr) {
    __shared__ uint32_t sk0[16], sk1[16];
    __shared__ float slog[4];
    int tid = threadIdx.x;
    int tloc = tid & 15;
    int b = tid >> 4;
    int t = blockIdx.x * 16 + tloc;

    if (tid < 16) {       // keys[t] = tf(key, 0, t)  (partitionable split)
        uint32_t a0, a1;
        tf2x32(0u, (uint32_t)(*seed_ptr), 0u, (uint32_t)(blockIdx.x * 16 + tid), a0, a1);
        sk0[tid] = a0; sk1[tid] = a1;
    } else if (tid >= 32 && tid < 36) {   // logits, built like the numpy reference
        double p = 0.1, s = 1.0 - 2.0 * 0.1;
        int k = tid - 32;
        double v = (k == 0) ? (double)(float)p
                 : (k == 1) ? (double)(float)s
                 : (k == 2) ? (double)(float)(s / (p + s))
                            : (double)(float)(p / (p + s));
        slog[k] = (float)log(v);
    }
    __syncthreads();

    if (t >= NSTEP) {     // pad steps 8189..8191 (never affect the output)
        g_snsp[b * T_LEN + t] = (uint8_t)(1u | (1u << 2));
        return;
    }
    uint32_t kt0 = sk0[tloc], kt1 = sk1[tloc];

    uint32_t bt[3];
#pragma unroll
    for (int k = 0; k < 3; k++) {   // bits[(16,3)][3b+k] = o0^o1 of tf(key_t, 0, j)
        uint32_t o0, o1;
        tf2x32(kt0, kt1, 0u, (uint32_t)(3 * b + k), o0, o1);
        bt[k] = o0 ^ o1;
    }

    float lp = slog[0], ls = slog[1], l21 = slog[2], l22 = slog[3];

    float g0 = gum_acc(bt[0]), g1 = gum_acc(bt[1]), g2 = gum_acc(bt[2]);
    float v0 = lp + g0, v1 = ls + g1, v2 = lp + g2;
    float w1 = l21 + g1, w2 = l22 + g2;

    float mmin = fminf(fminf(fabsf(v0 - v1), fabsf(v0 - v2)),
                       fminf(fabsf(v1 - v2), fabsf(w1 - w2)));
    if (mmin < 3e-5f) {   // tight argmax margin: redo exactly (DP logs, ~never)
        g0 = gum_precise(bt[0]); g1 = gum_precise(bt[1]); g2 = gum_precise(bt[2]);
        v0 = lp + g0; v1 = ls + g1; v2 = lp + g2;
        w1 = l21 + g1; w2 = l22 + g2;
    }

    int sn = 0; float best = v0;              // jnp.argmax first-max semantics
    if (v1 > best) { best = v1; sn = 1; }
    if (v2 > best) { sn = 2; }
    int sp = (w1 >= w2) ? 1 : 2;              // special row [-inf, w1, w2]

    g_snsp[b * T_LEN + t] = (uint8_t)(sn | (sp << 2));
}

// compose two 9-state maps packed as nibbles: (f ∘ g)(i) = f[g[i]]
__device__ __forceinline__ unsigned long long map_comp(unsigned long long f,
                                                       unsigned long long g) {
    unsigned long long r = 0ull;
#pragma unroll
    for (int i = 0; i < 9; i++) {
        uint32_t gi = (uint32_t)(g >> (4 * i)) & 15u;
        uint32_t fi = (uint32_t)(f >> (4 * gi)) & 15u;
        r |= (unsigned long long)fi << (4 * i);
    }
    return r;
}

// ---------------- K2: fused speculative chain (one block per batch) ----------------
__global__ void __launch_bounds__(576) k2_chain() {
    __shared__ uint8_t s_end[SEG_N][9];
    __shared__ unsigned long long s_map[SEG_N];
    int b = blockIdx.x;
    int tid = threadIdx.x;

    {   // ---- phase A: 64 segs x 9 speculative start states ----
        int seg = tid / 9, s0 = tid % 9;
        const uint4* src = (const uint4*)(g_snsp + b * T_LEN + seg * SEG_L);
        uint4 w[8];
#pragma unroll
        for (int q = 0; q < 8; q++) w[q] = __ldg(&src[q]);   // MLP=8 up front
        uint32_t cc = (((uint32_t)(s0 / 3)) << 2) | (uint32_t)(s0 % 3);
#pragma unroll
        for (int q = 0; q < 8; q++) {
            uint32_t ws[4] = {w[q].x, w[q].y, w[q].z, w[q].w};
#pragma unroll
            for (int wi = 0; wi < 4; wi++) {
                uint32_t word = ws[wi];
#pragma unroll
                for (int bi = 0; bi < 4; bi++) {
                    uint32_t byte = word >> (8 * bi);
                    uint32_t s = (cc == 9u) ? ((byte >> 2) & 3u) : (byte & 3u);
                    cc = (s << 2) | (cc >> 2);
                }
            }
        }
        s_end[seg][s0] = (uint8_t)((cc >> 2) * 3u + (cc & 3u));
    }
    __syncthreads();

    if (tid < SEG_N) {    // pack 9 end states into one nibble map
        unsigned long long m = 0ull;
#pragma unroll
        for (int i = 0; i < 9; i++)
            m |= (unsigned long long)s_end[tid][i] << (4 * i);
        s_map[tid] = m;
    }
    __syncthreads();

    // ---- phase B: Kogge-Stone inclusive prefix s_map[i] = m_i ∘ ... ∘ m_0 ----
#pragma unroll
    for (int d = 1; d < SEG_N; d <<= 1) {
        unsigned long long v;
        if (tid < SEG_N) {
            v = s_map[tid];
            if (tid >= d) v = map_comp(v, s_map[tid - d]);
        }
        __syncthreads();
        if (tid < SEG_N) s_map[tid] = v;
        __syncthreads();
    }

    if (tid == 0) g_smp[b * SMP_STRIDE + 15] = 1;   // pad byte: m(to=0) = 1

    if (tid < SEG_N) {    // ---- phase C: replay with true start ----
        int seg = tid;
        int i0 = (seg == 0) ? 4 : (int)((s_map[seg - 1] >> 16) & 15ull);
        const uint4* src = (const uint4*)(g_snsp + b * T_LEN + seg * SEG_L);
        uint4 w[8];
#pragma unroll
        for (int q = 0; q < 8; q++) w[q] = __ldg(&src[q]);
        uint32_t cc = (((uint32_t)(i0 / 3)) << 2) | (uint32_t)(i0 % 3);
        uint4* dst = (uint4*)(g_smp + b * SMP_STRIDE + 16 + seg * SEG_L);
#pragma unroll
        for (int q = 0; q < 8; q++) {
            uint32_t in[4] = {w[q].x, w[q].y, w[q].z, w[q].w};
            uint32_t out[4];
#pragma unroll
            for (int wi = 0; wi < 4; wi++) {
                uint32_t word = in[wi], ow = 0u;
#pragma unroll
                for (int bi = 0; bi < 4; bi++) {
                    uint32_t s = (cc == 9u) ? ((word >> (8 * bi + 2)) & 3u)
                                            : ((word >> (8 * bi)) & 3u);
                    cc = (s << 2) | (cc >> 2);
                    ow |= s << (8 * bi);
                }
                out[wi] = ow;
            }
            dst[q] = make_uint4(out[0], out[1], out[2], out[3]);
        }
    }
}

// ---------------- K4: gather, 2 distant quads / thread (ILP-2, dense requests) ----
// out[bi, to] = x[bi, to + m(b,to)];  m bytes live at g_smp[b*STRIDE + 15 + to]
__global__ void __launch_bounds__(256) k4_gather(const float* __restrict__ x,
                                                 float* __restrict__ out) {
    int t0 = blockIdx.x * blockDim.x + threadIdx.x;  // quad 0: outputs 4*t0 .. +3
    int t1 = t0 + 1024;                              // quad 1: outputs 4*t1 .. +3
    int bi = blockIdx.y;                             // b*256 + i
    int b = bi >> 8;

    // ---- all loads issued up front (6 independent requests) ----
    const uint32_t* mw = (const uint32_t*)(g_smp + b * SMP_STRIDE);
    uint32_t a0 = __ldg(&mw[t0 + 3]);
    uint32_t a1 = __ldg(&mw[t0 + 4]);
    uint32_t c0 = __ldg(&mw[t1 + 3]);
    uint32_t c1 = __ldg(&mw[t1 + 4]);

    const float* xr0 = x + (size_t)bi * 8192 + 4 * t0;
    const float* xr1 = x + (size_t)bi * 8192 + 4 * t1;
    float4 v0q = *(const float4*)xr0;
    float2 e0q = *(const float2*)(xr0 + 4);          // t0 <= 2046 always: safe
    float4 v1q = *(const float4*)xr1;
    float e1x = 0.f, e1y = 0.f;
    bool full1 = (t1 < 2047);
    if (full1) { float2 e = *(const float2*)(xr1 + 4); e1x = e.x; e1y = e.y; }

    uint32_t mw0 = __funnelshift_r(a0, a1, 24);      // m bytes for quad 0
    uint32_t mw1 = __funnelshift_r(c0, c1, 24);      // m bytes for quad 1

    bool al16 = ((bi & 1) == 0);
    float* obase = out + (size_t)bi * 8190;

    {   // ---- quad 0 (always full) ----
        uint32_t m0 = mw0 & 3u, m1 = (mw0 >> 8) & 3u,
                 m2 = (mw0 >> 16) & 3u, m3 = (mw0 >> 24) & 3u;
        float o0 = (m0 == 0u) ? v0q.x : ((m0 == 1u) ? v0q.y : v0q.z);
        float o1 = (m1 == 0u) ? v0q.y : ((m1 == 1u) ? v0q.z : v0q.w);
        float o2 = (m2 == 0u) ? v0q.z : ((m2 == 1u) ? v0q.w : e0q.x);
        float o3 = (m3 == 0u) ? v0q.w : ((m3 == 1u) ? e0q.x : e0q.y);
        float* orow = obase + 4 * t0;
        if (al16) {
            __stcs((float4*)orow, make_float4(o0, o1, o2, o3));
        } else {
            __stcs((float2*)orow, make_float2(o0, o1));
            __stcs((float2*)(orow + 2), make_float2(o2, o3));
        }
    }
    {   // ---- quad 1 (tail-guarded) ----
        uint32_t m0 = mw1 & 3u, m1 = (mw1 >> 8) & 3u,
                 m2 = (mw1 >> 16) & 3u, m3 = (mw1 >> 24) & 3u;
        float o0 = (m0 == 0u) ? v1q.x : ((m0 == 1u) ? v1q.y : v1q.z);
        float o1 = (m1 == 0u) ? v1q.y : ((m1 == 1u) ? v1q.z : v1q.w);
        float o2 = (m2 == 0u) ? v1q.z : ((m2 == 1u) ? v1q.w : e1x);
        float o3 = (m3 == 0u) ? v1q.w : ((m3 == 1u) ? e1x : e1y);
        float* orow = obase + 4 * t1;
        if (full1 & al16) {
            __stcs((float4*)orow, make_float4(o0, o1, o2, o3));
        } else {
            __stcs((float2*)orow, make_float2(o0, o1));
            if (full1) __stcs((float2*)(orow + 2), make_float2(o2, o3));
        }
    }
}

extern "C" void kernel_launch(void* const* d_in, const int* in_sizes, int n_in,
                              void* d_out, int out_size) {
    const float* x = (const float*)d_in[0];
    const int* seed = (const int*)d_in[1];
    float* out = (float*)d_out;

    k1_gen<<<512, 256>>>(seed);           // 512 blocks of (16 t x 16 b), logits fused
    k2_chain<<<16, 576>>>();              // one block per batch: spec + prefix + replay
    dim3 grid(4, 4096);                   // 4*256 = 1024 threads/row, 2 quads each
    k4_gather<<<grid, 256>>>(x, out);
}